// round 7
// baseline (speedup 1.0000x reference)
#include <cuda_runtime.h>
#include <math.h>

#define B    32
#define L    2048
#define DC   512
#define DQ   1024
#define H    256
#define NW   7
#define NBLK 256
#define NTHR 256

// scratch (no allocations allowed)
__device__ float g_h[B][H];         // tanh'd hidden for stat projection
__device__ float g_qt[B][H];        // query-part of MLP pre-activation + b1
__device__ float g_spart[B][NW][4]; // per-slice partial scores
__device__ unsigned g_cnt[B];       // producer arrivals (8 per replay, monotonic)
__device__ unsigned g_cnt2[B];      // slice arrivals   (4 per replay, monotonic)

typedef unsigned long long ull;

__device__ __forceinline__ ull pack2(float x) {
    ull r;
    asm("mov.b64 %0, {%1, %1};" : "=l"(r) : "f"(x));
    return r;
}
__device__ __forceinline__ void ffma2(ull& acc, ull a, ull b) {
    asm("fma.rn.f32x2 %0, %1, %2, %0;" : "+l"(acc) : "l"(a), "l"(b));
}

__global__ void __launch_bounds__(NTHR)
k_all(const float* __restrict__ query,
      const float* __restrict__ ctx,
      const float* __restrict__ kappa_prev,
      const float* __restrict__ Wq,
      const float* __restrict__ bq,
      const float* __restrict__ Ws,
      const float* __restrict__ bs,
      const float* __restrict__ W1,
      const float* __restrict__ b1,
      const float* __restrict__ W2,
      const float* __restrict__ b2,
      float* __restrict__ out)
{
    int bx = blockIdx.x;        // 0..255
    int t  = threadIdx.x;       // 0..255
    int lane = t & 31;
    int wid  = t >> 5;          // 0..7

    int b   = bx >> 3;          // batch
    int sub = bx & 7;
    int m   = sub >> 2;         // 0: Wq (h), 1: W1 query-half (qt)
    int jc  = sub & 3;          // 64-col chunk

    __shared__ union {
        struct { float q[DQ]; float red[16 * 64]; } p;                     //  8 KB
        struct { float ctx[NW * DC];                                       // 14 KB
                 float red[16 * NW * 64];                                  // 28 KB
                 float hid[NW * 64];                                       // 1.75 KB
                 float qt[64]; float params[4]; } c;
    } sm;
    __shared__ float swr[3][8];
    __shared__ float spw[NW];
    __shared__ unsigned s_old;
    __shared__ int s_last;

    // ================= Producer: full-depth dot for (b, m, 64-j chunk) =====
    {
        const float* W = m ? (W1 + (size_t)DC * H) : Wq;
        int j0 = jc * 64;

        ((float4*)sm.p.q)[t] = ((const float4*)(query + (size_t)b * DQ))[t];
        __syncthreads();

        int jt = t & 15;            // 4 j each
        int ig = t >> 4;            // 16 groups x 64 i-rows
        ull a01 = 0ull, a23 = 0ull;
        const float* qs = sm.p.q + ig * 64;
        const char*  Wr = (const char*)(W + (size_t)(ig * 64) * H + j0 + jt * 4);
#pragma unroll 8
        for (int ii = 0; ii < 64; ii++) {
            ulonglong2 wv = *(const ulonglong2*)(Wr + (size_t)ii * (H * 4));
            ull qq = pack2(qs[ii]);
            ffma2(a01, qq, wv.x);
            ffma2(a23, qq, wv.y);
        }
        *((ulonglong2*)&sm.p.red[ig * 64 + jt * 4]) = make_ulonglong2(a01, a23);
        __syncthreads();

        if (t < 64) {
            float s = 0.f;
#pragma unroll
            for (int g = 0; g < 16; g++) s += sm.p.red[g * 64 + t];
            int j = j0 + t;
            if (m == 0) g_h[b][j]  = tanhf(s + bq[j]);
            else        g_qt[b][j] = s + b1[j];
        }
        // zero-fill this block's p_ctx chunk (covers batch b's own row)
        out[(size_t)B * DC + (size_t)bx * NTHR + t] = 0.f;
        __syncthreads();
        if (t == 0) {
            __threadfence();
            s_old = atomicAdd(&g_cnt[b], 1u);
        }
    }

    if (m != 0) return;             // only m==0 blocks continue as consumers
    int slice = jc;

    // ================= Consumer: wait for batch b's 8 producers ============
    __syncthreads();
    if (t == 0) {
        unsigned target = ((s_old >> 3) + 1u) << 3;   // monotonic across replays
        while (*(volatile unsigned*)&g_cnt[b] < target) { }
        __threadfence();
    }
    __syncthreads();

    // ---- params: stat = h @ Ws + bs ----
    float hv = __ldcg(&g_h[b][t]);
    float v0 = hv * Ws[t * 3 + 0];
    float v1 = hv * Ws[t * 3 + 1];
    float v2 = hv * Ws[t * 3 + 2];
#pragma unroll
    for (int o = 16; o; o >>= 1) {
        v0 += __shfl_down_sync(0xffffffffu, v0, o);
        v1 += __shfl_down_sync(0xffffffffu, v1, o);
        v2 += __shfl_down_sync(0xffffffffu, v2, o);
    }
    if (lane == 0) { swr[0][wid] = v0; swr[1][wid] = v1; swr[2][wid] = v2; }
    if (t < 64) sm.c.qt[t] = __ldcg(&g_qt[b][slice * 64 + t]);
    __syncthreads();
    if (t == 0) {
        float s0 = bs[0], s1 = bs[1], s2 = bs[2];
#pragma unroll
        for (int w = 0; w < 8; w++) { s0 += swr[0][w]; s1 += swr[1][w]; s2 += swr[2][w]; }
        float kappa = expf(s2) + kappa_prev[b];
        sm.c.params[0] = expf(s0);
        sm.c.params[1] = expf(s1);
        sm.c.params[2] = kappa;
        sm.c.params[3] = rintf(kappa);          // jnp.round = round-half-even
    }
    __syncthreads();
    int center = (int)sm.c.params[3];

    // ---- stage 7 ctx rows (zero-filled out of range) ----
    for (int cix = t; cix < NW * (DC / 4); cix += NTHR) {
        int w  = cix / (DC / 4);
        int i4 = cix % (DC / 4);
        int l  = center - 3 + w;
        float4 v = make_float4(0.f, 0.f, 0.f, 0.f);
        if (l >= 0 && l < L)
            v = ((const float4*)(ctx + ((size_t)b * L + l) * DC))[i4];
        *((float4*)&sm.c.ctx[w * DC + i4 * 4]) = v;
    }
    __syncthreads();

    // ---- ctx-MLP slice: 16 i-groups x 16 j-threads (4 j each) ----
    {
        int jt = t & 15;
        int ig = t >> 4;            // 16 groups x 32 i-rows
        int j0 = slice * 64 + jt * 4;
        int i0 = ig * 32;

        ull ac[NW][2];
#pragma unroll
        for (int w = 0; w < NW; w++) { ac[w][0] = 0ull; ac[w][1] = 0ull; }

        const char* Wr = (const char*)(W1 + (size_t)i0 * H + j0);
#pragma unroll 4
        for (int ii = 0; ii < 32; ii++) {
            ulonglong2 wv = *(const ulonglong2*)(Wr + (size_t)ii * (H * 4));
#pragma unroll
            for (int w = 0; w < NW; w++) {
                ull cc = pack2(sm.c.ctx[w * DC + i0 + ii]);
                ffma2(ac[w][0], cc, wv.x);
                ffma2(ac[w][1], cc, wv.y);
            }
        }
#pragma unroll
        for (int w = 0; w < NW; w++)
            *((ulonglong2*)&sm.c.red[(ig * NW + w) * 64 + jt * 4]) =
                make_ulonglong2(ac[w][0], ac[w][1]);
    }
    __syncthreads();

    // ---- hidden: tanh + W2 weight, 448 (w,j) pairs over 256 threads ----
    for (int idx = t; idx < NW * 64; idx += NTHR) {
        int w = idx >> 6;
        int j = idx & 63;
        float s = sm.c.qt[j];
#pragma unroll
        for (int g = 0; g < 16; g++) s += sm.c.red[(g * NW + w) * 64 + j];
        sm.c.hid[idx] = tanhf(s) * W2[slice * 64 + j];
    }
    __syncthreads();

    // ---- per-window score: warp w reduces its 64 values ----
    if (wid < NW) {
        float v = sm.c.hid[wid * 64 + lane] + sm.c.hid[wid * 64 + 32 + lane];
#pragma unroll
        for (int o = 16; o; o >>= 1)
            v += __shfl_down_sync(0xffffffffu, v, o);
        if (lane == 0) g_spart[b][wid][slice] = v;
    }
    __syncthreads();

    // ---- last-arriving slice finalizes (sctx already in smem) ----
    if (t == 0) {
        __threadfence();
        unsigned old2 = atomicAdd(&g_cnt2[b], 1u);
        s_last = ((old2 & 3u) == 3u);
    }
    __syncthreads();
    if (!s_last) return;

    if (t == 0) {
        __threadfence();            // acquire other slices' g_spart
        float alpha = sm.c.params[0], beta = sm.c.params[1], kappa = sm.c.params[2];
        float b2v = b2[0];
        float pw[NW], psum = 0.f;
#pragma unroll
        for (int w = 0; w < NW; w++) {
            int l = center - 3 + w;
            float p = 0.f;
            if (l >= 0 && l < L) {
                float sc = b2v;
#pragma unroll
                for (int s2 = 0; s2 < 4; s2++) sc += __ldcg(&g_spart[b][w][s2]);
                float d = (float)l - kappa;
                p = alpha * expf(sc - beta * d * d);
            }
            pw[w] = p;
            psum += p;
        }
        float inv = 1.f / psum;
#pragma unroll
        for (int w = 0; w < NW; w++) spw[w] = pw[w] * inv;
    }
    __syncthreads();

    // expected_ctx from smem ctx rows (512 over 256 threads)
    for (int d = t; d < DC; d += NTHR) {
        float acc = 0.f;
#pragma unroll
        for (int w = 0; w < NW; w++)
            acc += spw[w] * sm.c.ctx[w * DC + d];
        out[(size_t)b * DC + d] = acc;
    }
    // sparse p_ctx writes (row zero-filled by batch b's own producers)
    if (t < NW) {
        int l = center - 3 + t;
        if (l >= 0 && l < L)
            out[(size_t)B * DC + (size_t)b * L + l] = spw[t];
    }
}

// ---------------------------------------------------------------------------
extern "C" void kernel_launch(void* const* d_in, const int* in_sizes, int n_in,
                              void* d_out, int out_size)
{
    const float* query = (const float*)d_in[0];
    const float* ctx   = (const float*)d_in[1];
    const float* kprev = (const float*)d_in[2];
    const float* Wq    = (const float*)d_in[3];
    const float* bq    = (const float*)d_in[4];
    const float* Ws    = (const float*)d_in[5];
    const float* bs    = (const float*)d_in[6];
    const float* W1    = (const float*)d_in[7];
    const float* b1    = (const float*)d_in[8];
    const float* W2    = (const float*)d_in[9];
    const float* b2    = (const float*)d_in[10];

    k_all<<<NBLK, NTHR>>>(query, ctx, kprev, Wq, bq, Ws, bs, W1, b1, W2, b2,
                          (float*)d_out);
}

// round 8
// speedup vs baseline: 1.0012x; 1.0012x over previous
#include <cuda_runtime.h>
#include <math.h>

#define B    32
#define L    2048
#define DC   512
#define DQ   1024
#define H    256
#define NW   7
#define NIC  16          // i-chunks for query GEMMs (1024/64)
#define ICR  64          // rows per i-chunk
#define NBLK 128
#define NTHR 512

// scratch (no allocations allowed)
__device__ float g_pre[2][NIC][B][H];   // [0]=h-pre partials, [1]=q-part partials
__device__ float g_spart[B][NW][4];     // per-slice partial scores
__device__ unsigned g_done[2];          // per-plane producer arrivals (64/replay, monotonic)
__device__ unsigned g_cnt2[B];          // slice arrivals (4/replay, monotonic)

__global__ void __launch_bounds__(NTHR, 1)
k_all(const float* __restrict__ query,
      const float* __restrict__ ctx,
      const float* __restrict__ kappa_prev,
      const float* __restrict__ Wq,
      const float* __restrict__ bq,
      const float* __restrict__ Ws,
      const float* __restrict__ bs,
      const float* __restrict__ W1,
      const float* __restrict__ b1,
      const float* __restrict__ W2,
      const float* __restrict__ b2,
      float* __restrict__ out)
{
    int bx = blockIdx.x;        // 0..127
    int t  = threadIdx.x;       // 0..511
    int lane = t & 31;
    int wid  = t >> 5;          // 0..15

    __shared__ union {
        struct { float W[ICR * 64]; float q[B * ICR]; } p1;               // 24 KB
        struct { float ctx[NW * DC];                                      // 14 KB
                 float red[16 * NW * 64];                                 // 28 KB
                 float hid[NW * 64];                                      // 1.75 KB
                 float qt[64]; float params[4]; } p2;
    } sm;
    __shared__ float swr[3][16];
    __shared__ float spw[NW];
    __shared__ unsigned s_epoch;
    __shared__ int s_last;

    // ================= Phase 1: query GEMM partials + p_ctx zero-fill ======
    out[(size_t)B * DC + (size_t)bx * NTHR + t] = 0.f;

    {
        int m  = bx & 1;            // 0: Wq, 1: W1 query-half
        int jc = (bx >> 1) & 3;     // j-chunk (64 cols)
        int ic = bx >> 3;           // i-chunk (64 rows)
        const float* W = m ? (W1 + (size_t)DC * H) : Wq;
        int i0 = ic * ICR;
        int j0 = jc * 64;

        for (int idx = t; idx < ICR * 16; idx += NTHR) {
            int r  = idx >> 4;
            int c4 = idx & 15;
            *((float4*)&sm.p1.W[r * 64 + c4 * 4]) =
                *((const float4*)(W + (size_t)(i0 + r) * H + j0 + c4 * 4));
        }
        {
            int b8 = t >> 4;
            int c4 = t & 15;
            *((float4*)&sm.p1.q[b8 * ICR + c4 * 4]) =
                *((const float4*)(query + (size_t)b8 * DQ + i0 + c4 * 4));
        }
        __syncthreads();

        int jt = t & 15;            // 4 j's each
        int bb = t >> 4;            // batch 0..31
        float a0 = 0.f, a1 = 0.f, a2 = 0.f, a3 = 0.f;
#pragma unroll 8
        for (int i = 0; i < ICR; i++) {
            float4 w = *((const float4*)&sm.p1.W[i * 64 + jt * 4]);
            float qv = sm.p1.q[bb * ICR + i];
            a0 += qv * w.x; a1 += qv * w.y; a2 += qv * w.z; a3 += qv * w.w;
        }
        float4 r4 = make_float4(a0, a1, a2, a3);
        *((float4*)&g_pre[m][ic][bb][j0 + jt * 4]) = r4;
        __syncthreads();

        if (t == 0) {
            __threadfence();
            unsigned old = atomicAdd(&g_done[m], 1u);
            s_epoch = old >> 6;                    // 64 arrivals per plane/replay
        }
    }
    __syncthreads();
    unsigned target = (s_epoch + 1u) << 6;

    // ================= Phase 2: consumer for (b, slice) ====================
    int b     = bx >> 2;
    int slice = bx & 3;

    // ---- wait for h plane (m=0) only ----
    if (t == 0) {
        while (*(volatile unsigned*)&g_done[0] < target) { }
        __threadfence();
    }
    __syncthreads();

    // ---- params: h-pre reduce + tanh, stat = h @ Ws + bs ----
    float hval = 0.f;
    if (t < H) {
        float s = bq[t];
#pragma unroll
        for (int ic = 0; ic < NIC; ic++) s += g_pre[0][ic][b][t];
        hval = tanhf(s);
    }
    float v0 = 0.f, v1 = 0.f, v2 = 0.f;
    if (t < H) {
        v0 = hval * Ws[t * 3 + 0];
        v1 = hval * Ws[t * 3 + 1];
        v2 = hval * Ws[t * 3 + 2];
    }
#pragma unroll
    for (int o = 16; o; o >>= 1) {
        v0 += __shfl_down_sync(0xffffffffu, v0, o);
        v1 += __shfl_down_sync(0xffffffffu, v1, o);
        v2 += __shfl_down_sync(0xffffffffu, v2, o);
    }
    if (lane == 0) { swr[0][wid] = v0; swr[1][wid] = v1; swr[2][wid] = v2; }
    __syncthreads();
    if (t == 0) {
        float s0 = bs[0], s1 = bs[1], s2 = bs[2];
#pragma unroll
        for (int w = 0; w < 16; w++) { s0 += swr[0][w]; s1 += swr[1][w]; s2 += swr[2][w]; }
        float kappa = expf(s2) + kappa_prev[b];
        sm.p2.params[0] = expf(s0);
        sm.p2.params[1] = expf(s1);
        sm.p2.params[2] = kappa;
        sm.p2.params[3] = rintf(kappa);         // jnp.round = round-half-even
    }
    __syncthreads();
    int center = (int)sm.p2.params[3];

    // ---- stage 7 ctx rows (zero-filled out of range) ----
    for (int c = t; c < NW * (DC / 4); c += NTHR) {
        int w  = c / (DC / 4);
        int i4 = c % (DC / 4);
        int l  = center - 3 + w;
        float4 v = make_float4(0.f, 0.f, 0.f, 0.f);
        if (l >= 0 && l < L)
            v = ((const float4*)(ctx + ((size_t)b * L + l) * DC))[i4];
        *((float4*)&sm.p2.ctx[w * DC + i4 * 4]) = v;
    }
    __syncthreads();

    // ---- ctx-MLP: 32 i-groups x 16 j-threads (4 j each) ----
    {
        int igp = t >> 4;           // 0..31, 16 i-rows each
        int jt  = t & 15;
        int j0  = slice * 64 + jt * 4;
        int i0  = igp * 16;

        float ac[NW][4];
#pragma unroll
        for (int w = 0; w < NW; w++)
#pragma unroll
            for (int k = 0; k < 4; k++) ac[w][k] = 0.f;

#pragma unroll 4
        for (int ii = 0; ii < 16; ii++) {
            float4 wv = *((const float4*)(W1 + (size_t)(i0 + ii) * H + j0));
#pragma unroll
            for (int w = 0; w < NW; w++) {
                float c = sm.p2.ctx[w * DC + i0 + ii];
                ac[w][0] += c * wv.x;
                ac[w][1] += c * wv.y;
                ac[w][2] += c * wv.z;
                ac[w][3] += c * wv.w;
            }
        }

        // fold igp pairs within warp (lanes 0-15 keep), dump once
#pragma unroll
        for (int w = 0; w < NW; w++)
#pragma unroll
            for (int k = 0; k < 4; k++) {
                float v = ac[w][k];
                v += __shfl_xor_sync(0xffffffffu, v, 16);
                if (lane < 16)
                    sm.p2.red[(wid * NW + w) * 64 + jt * 4 + k] = v;
            }
    }

    // ---- wait for qt plane (m=1); overlapped with MLP above ----
    if (t == 0) {
        while (*(volatile unsigned*)&g_done[1] < target) { }
        __threadfence();
    }
    __syncthreads();
    if (t < 64) {
        int j = slice * 64 + t;
        float qt = b1[j];
#pragma unroll
        for (int ic = 0; ic < NIC; ic++) qt += g_pre[1][ic][b][j];
        sm.p2.qt[t] = qt;
    }
    __syncthreads();

    // ---- hidden: tanh + W2 weight, 448 (w,j) pairs ----
    if (t < NW * 64) {
        int w = t >> 6;
        int j = t & 63;
        float s = sm.p2.qt[j];
#pragma unroll
        for (int p = 0; p < 16; p++)
            s += sm.p2.red[(p * NW + w) * 64 + j];
        sm.p2.hid[t] = tanhf(s) * W2[slice * 64 + j];
    }
    __syncthreads();

    // ---- per-window score: warp w reduces its 64 values ----
    if (wid < NW) {
        float v = sm.p2.hid[wid * 64 + lane] + sm.p2.hid[wid * 64 + 32 + lane];
#pragma unroll
        for (int o = 16; o; o >>= 1)
            v += __shfl_down_sync(0xffffffffu, v, o);
        if (lane == 0) g_spart[b][wid][slice] = v;
    }
    __syncthreads();

    // ---- last-arriving slice of this batch finalizes ----
    if (t == 0) {
        __threadfence();
        unsigned old2 = atomicAdd(&g_cnt2[b], 1u);
        s_last = ((old2 & 3u) == 3u);
    }
    __syncthreads();
    if (!s_last) return;

    if (t == 0) {
        __threadfence();            // acquire other slices' g_spart
        float alpha = sm.p2.params[0], beta = sm.p2.params[1], kappa = sm.p2.params[2];
        float b2v = b2[0];
        float pw[NW], psum = 0.f;
#pragma unroll
        for (int w = 0; w < NW; w++) {
            int l = center - 3 + w;
            float p = 0.f;
            if (l >= 0 && l < L) {
                float sc = b2v;
#pragma unroll
                for (int s2 = 0; s2 < 4; s2++) sc += *(volatile float*)&g_spart[b][w][s2];
                float d = (float)l - kappa;
                p = alpha * expf(sc - beta * d * d);
            }
            pw[w] = p;
            psum += p;
        }
        float inv = 1.f / psum;
#pragma unroll
        for (int w = 0; w < NW; w++) spw[w] = pw[w] * inv;
    }
    __syncthreads();

    // expected_ctx from smem-staged ctx rows (512 threads = DC)
    {
        float acc = 0.f;
#pragma unroll
        for (int w = 0; w < NW; w++)
            acc += spw[w] * sm.p2.ctx[w * DC + t];
        out[(size_t)b * DC + t] = acc;
    }
    // sparse p_ctx writes (region zero-filled in phase 1 by co-resident blocks;
    // ordered by the m=0/m=1 plane waits which cover all 128 blocks' phase 1)
    if (t < NW) {
        int l = center - 3 + t;
        if (l >= 0 && l < L)
            out[(size_t)B * DC + (size_t)b * L + l] = spw[t];
    }
}

// ---------------------------------------------------------------------------
extern "C" void kernel_launch(void* const* d_in, const int* in_sizes, int n_in,
                              void* d_out, int out_size)
{
    const float* query = (const float*)d_in[0];
    const float* ctx   = (const float*)d_in[1];
    const float* kprev = (const float*)d_in[2];
    const float* Wq    = (const float*)d_in[3];
    const float* bq    = (const float*)d_in[4];
    const float* Ws    = (const float*)d_in[5];
    const float* bs    = (const float*)d_in[6];
    const float* W1    = (const float*)d_in[7];
    const float* b1    = (const float*)d_in[8];
    const float* W2    = (const float*)d_in[9];
    const float* b2    = (const float*)d_in[10];

    k_all<<<NBLK, NTHR>>>(query, ctx, kprev, Wq, bq, Ws, bs, W1, b1, W2, b2,
                          (float*)d_out);
}

// round 9
// speedup vs baseline: 1.2805x; 1.2790x over previous
#include <cuda_runtime.h>
#include <math.h>

#define B    32
#define L    2048
#define DC   512
#define DQ   1024
#define H    256
#define NW   7
#define NIC  16          // i-chunks for query GEMMs (1024/64)
#define ICR  64          // rows per i-chunk
#define NBLK 128
#define NTHR 512

// scratch (no allocations allowed)
__device__ float g_pre[2][NIC][B][H];   // [0]=h-pre partials, [1]=q-part of MLP partials
__device__ float g_spart[B][NW][4];     // per-slice partial scores
__device__ unsigned g_cnt2[B][32];      // per-batch arrival counters, 128B stride
__device__ unsigned g_sub[8][32];       // barrier sub-counters, 128B stride
__device__ unsigned g_mid;              // barrier master counter
__device__ unsigned g_gen;              // barrier generation (monotonic across replays)

// two-level sense-reversal barrier: 8 padded sub-counters -> master -> gen
__device__ __forceinline__ void grid_sync(int bx)
{
    __syncthreads();
    if (threadIdx.x == 0) {
        __threadfence();
        unsigned gen = *(volatile unsigned*)&g_gen;
        unsigned o1 = atomicAdd(&g_sub[bx & 7][0], 1u);
        if ((o1 & 15u) == 15u) {                      // last of this 16-group
            unsigned o2 = atomicAdd(&g_mid, 1u);
            if ((o2 & 7u) == 7u) {                    // last group overall
                __threadfence();
                *(volatile unsigned*)&g_gen = gen + 1u;
            }
        }
        while (*(volatile unsigned*)&g_gen == gen) { }
        __threadfence();
    }
    __syncthreads();
}

__global__ void __launch_bounds__(NTHR, 1)
k_all(const float* __restrict__ query,
      const float* __restrict__ ctx,
      const float* __restrict__ kappa_prev,
      const float* __restrict__ Wq,
      const float* __restrict__ bq,
      const float* __restrict__ Ws,
      const float* __restrict__ bs,
      const float* __restrict__ W1,
      const float* __restrict__ b1,
      const float* __restrict__ W2,
      const float* __restrict__ b2,
      float* __restrict__ out)
{
    int bx = blockIdx.x;        // 0..127
    int t  = threadIdx.x;       // 0..511
    int lane = t & 31;
    int wid  = t >> 5;          // 0..15

    __shared__ union {
        struct { float W[ICR * 64]; float q[B * ICR]; } p1;               // 24 KB
        struct { float ctx[NW * DC];                                      // 14 KB
                 float red[16 * NW * 64];                                 // 28 KB
                 float qt[64]; float params[4]; } p2;
    } sm;
    __shared__ float swr[3][16];
    __shared__ float swr3[NW][2];
    __shared__ float spw[NW];
    __shared__ int   s_last;

    // ================= Phase 1: query GEMM partials + p_ctx zero-fill ======
    out[(size_t)B * DC + (size_t)bx * NTHR + t] = 0.f;

    {
        int m  = bx & 1;            // 0: Wq, 1: W1 query-half
        int jc = (bx >> 1) & 3;     // j-chunk (64 cols)
        int ic = bx >> 3;           // i-chunk (64 rows)
        const float* W = m ? (W1 + (size_t)DC * H) : Wq;
        int i0 = ic * ICR;
        int j0 = jc * 64;

        for (int idx = t; idx < ICR * 16; idx += NTHR) {
            int r  = idx >> 4;
            int c4 = idx & 15;
            *((float4*)&sm.p1.W[r * 64 + c4 * 4]) =
                *((const float4*)(W + (size_t)(i0 + r) * H + j0 + c4 * 4));
        }
        {
            int b8 = t >> 4;
            int c4 = t & 15;
            *((float4*)&sm.p1.q[b8 * ICR + c4 * 4]) =
                *((const float4*)(query + (size_t)b8 * DQ + i0 + c4 * 4));
        }
        __syncthreads();

        int jt = t & 15;            // 4 j's each
        int bb = t >> 4;            // batch 0..31
        float a0 = 0.f, a1 = 0.f, a2 = 0.f, a3 = 0.f;
#pragma unroll 8
        for (int i = 0; i < ICR; i++) {
            float4 w = *((const float4*)&sm.p1.W[i * 64 + jt * 4]);
            float qv = sm.p1.q[bb * ICR + i];
            a0 += qv * w.x; a1 += qv * w.y; a2 += qv * w.z; a3 += qv * w.w;
        }
        float4 r4 = make_float4(a0, a1, a2, a3);
        *((float4*)&g_pre[m][ic][bb][j0 + jt * 4]) = r4;
    }

    grid_sync(bx);

    // ================= Phase 2: params + ctx-MLP slice + last-block finalize
    int b     = bx >> 2;
    int slice = bx & 3;

    // prefetch this block's W1 ctx-slice into L2 (overlaps params + ctx stage)
    {
        const char* base = (const char*)(W1 + (size_t)t * H + slice * 64);
        asm volatile("prefetch.global.L2 [%0];" :: "l"(base));
        asm volatile("prefetch.global.L2 [%0];" :: "l"(base + 128));
    }

    // h-pre reduce + tanh (t<256), qtot for this slice (t<64)
    float hval = 0.f;
    if (t < H) {
        float s = bq[t];
#pragma unroll
        for (int ic = 0; ic < NIC; ic++) s += g_pre[0][ic][b][t];
        hval = tanhf(s);
    }
    if (t < 64) {
        int j = slice * 64 + t;
        float qt = b1[j];
#pragma unroll
        for (int ic = 0; ic < NIC; ic++) qt += g_pre[1][ic][b][j];
        sm.p2.qt[t] = qt;
    }
    // stat = h @ Ws + bs
    float v0 = 0.f, v1 = 0.f, v2 = 0.f;
    if (t < H) {
        v0 = hval * Ws[t * 3 + 0];
        v1 = hval * Ws[t * 3 + 1];
        v2 = hval * Ws[t * 3 + 2];
    }
#pragma unroll
    for (int o = 16; o; o >>= 1) {
        v0 += __shfl_down_sync(0xffffffffu, v0, o);
        v1 += __shfl_down_sync(0xffffffffu, v1, o);
        v2 += __shfl_down_sync(0xffffffffu, v2, o);
    }
    if (lane == 0) { swr[0][wid] = v0; swr[1][wid] = v1; swr[2][wid] = v2; }
    __syncthreads();
    if (t == 0) {
        float s0 = bs[0], s1 = bs[1], s2 = bs[2];
#pragma unroll
        for (int w = 0; w < 16; w++) { s0 += swr[0][w]; s1 += swr[1][w]; s2 += swr[2][w]; }
        float kappa = expf(s2) + kappa_prev[b];
        sm.p2.params[0] = expf(s0);
        sm.p2.params[1] = expf(s1);
        sm.p2.params[2] = kappa;
        sm.p2.params[3] = rintf(kappa);     // jnp.round = round-half-even
    }
    __syncthreads();
    int center = (int)sm.p2.params[3];

    // stage 7 ctx rows (zero-filled out of range)
    for (int c = t; c < NW * (DC / 4); c += NTHR) {
        int w  = c / (DC / 4);
        int i4 = c % (DC / 4);
        int l  = center - 3 + w;
        float4 v = make_float4(0.f, 0.f, 0.f, 0.f);
        if (l >= 0 && l < L)
            v = ((const float4*)(ctx + ((size_t)b * L + l) * DC))[i4];
        *((float4*)&sm.p2.ctx[w * DC + i4 * 4]) = v;
    }
    __syncthreads();

    // ctx-MLP: 32 i-groups x 16 j-threads (4 j each)
    {
        int igp = t >> 4;           // 0..31, 16 i-rows each
        int jt  = t & 15;
        int j0  = slice * 64 + jt * 4;
        int i0  = igp * 16;

        float ac[NW][4];
#pragma unroll
        for (int w = 0; w < NW; w++)
#pragma unroll
            for (int k = 0; k < 4; k++) ac[w][k] = 0.f;

#pragma unroll 4
        for (int ii = 0; ii < 16; ii++) {
            float4 wv = *((const float4*)(W1 + (size_t)(i0 + ii) * H + j0));
#pragma unroll
            for (int w = 0; w < NW; w++) {
                float c = sm.p2.ctx[w * DC + i0 + ii];
                ac[w][0] += c * wv.x;
                ac[w][1] += c * wv.y;
                ac[w][2] += c * wv.z;
                ac[w][3] += c * wv.w;
            }
        }

        // fold igp pairs within warp (lanes 0-15 keep), dump once
#pragma unroll
        for (int w = 0; w < NW; w++)
#pragma unroll
            for (int k = 0; k < 4; k++) {
                float v = ac[w][k];
                v += __shfl_xor_sync(0xffffffffu, v, 16);
                if (lane < 16)
                    sm.p2.red[(wid * NW + w) * 64 + jt * 4 + k] = v;
            }
    }
    __syncthreads();

    // single pass: 448 threads finish all 7 windows
    {
        float contrib = 0.f;
        if (t < NW * 64) {
            int w = t >> 6;
            int j = t & 63;
            float hsum = sm.p2.qt[j];
#pragma unroll
            for (int p = 0; p < 16; p++)
                hsum += sm.p2.red[(p * NW + w) * 64 + j];
            contrib = tanhf(hsum) * W2[slice * 64 + j];
        }
#pragma unroll
        for (int o = 16; o; o >>= 1)
            contrib += __shfl_down_sync(0xffffffffu, contrib, o);
        if (lane == 0 && wid < NW * 2) swr3[wid >> 1][wid & 1] = contrib;
        __syncthreads();
        if (t < NW)
            g_spart[b][t][slice] = swr3[t][0] + swr3[t][1];
    }
    __syncthreads();

    // arrival counter: last slice block of this batch finalizes
    if (t == 0) {
        __threadfence();
        unsigned old = atomicAdd(&g_cnt2[b][0], 1u);
        s_last = ((old & 3u) == 3u);
    }
    __syncthreads();
    if (!s_last) return;

    // ================= finalize (winner block; sctx already in smem) =======
    if (t == 0) {
        __threadfence();    // acquire: other slices' g_spart stores
        float alpha = sm.p2.params[0], beta = sm.p2.params[1], kappa = sm.p2.params[2];
        float b2v = b2[0];
        float pw[NW], psum = 0.f;
#pragma unroll
        for (int w = 0; w < NW; w++) {
            int l = center - 3 + w;
            float p = 0.f;
            if (l >= 0 && l < L) {
                float sc = b2v;
#pragma unroll
                for (int s2 = 0; s2 < 4; s2++) sc += *(volatile float*)&g_spart[b][w][s2];
                float d = (float)l - kappa;
                p = alpha * expf(sc - beta * d * d);
            }
            pw[w] = p;
            psum += p;
        }
        float inv = 1.f / psum;
#pragma unroll
        for (int w = 0; w < NW; w++) spw[w] = pw[w] * inv;
    }
    __syncthreads();

    // expected_ctx from smem-staged ctx rows (512 threads = DC)
    {
        float acc = 0.f;
#pragma unroll
        for (int w = 0; w < NW; w++)
            acc += spw[w] * sm.p2.ctx[w * DC + t];
        out[(size_t)b * DC + t] = acc;
    }
    // sparse p_ctx writes (rest zero-filled in phase 1, ordered by grid_sync)
    if (t < NW) {
        int l = center - 3 + t;
        if (l >= 0 && l < L)
            out[(size_t)B * DC + (size_t)b * L + l] = spw[t];
    }
}

// ---------------------------------------------------------------------------
extern "C" void kernel_launch(void* const* d_in, const int* in_sizes, int n_in,
                              void* d_out, int out_size)
{
    const float* query = (const float*)d_in[0];
    const float* ctx   = (const float*)d_in[1];
    const float* kprev = (const float*)d_in[2];
    const float* Wq    = (const float*)d_in[3];
    const float* bq    = (const float*)d_in[4];
    const float* Ws    = (const float*)d_in[5];
    const float* bs    = (const float*)d_in[6];
    const float* W1    = (const float*)d_in[7];
    const float* b1    = (const float*)d_in[8];
    const float* W2    = (const float*)d_in[9];
    const float* b2    = (const float*)d_in[10];

    k_all<<<NBLK, NTHR>>>(query, ctx, kprev, Wq, bq, Ws, bs, W1, b1, W2, b2,
                          (float*)d_out);
}

// round 10
// speedup vs baseline: 1.4341x; 1.1199x over previous
#include <cuda_runtime.h>
#include <math.h>

#define B    32
#define L    2048
#define DC   512
#define DQ   1024
#define H    256
#define NW   7
#define NIC  16          // i-chunks for query GEMMs (1024/64)
#define ICR  64          // rows per i-chunk
#define NBLK 128
#define NTHR 512

// scratch (no allocations allowed)
__device__ float g_pre[2][NIC][B][H];   // [0]=h-pre partials, [1]=q-part of MLP partials
__device__ float g_spart[B][NW][4];     // per-slice partial scores
__device__ unsigned g_cnt[B];           // per-batch arrival counters (monotonic)
__device__ unsigned g_bar_count = 0;
__device__ unsigned g_bar_gen   = 0;    // monotonic across graph replays

__device__ __forceinline__ void grid_sync()
{
    __syncthreads();
    if (threadIdx.x == 0) {
        __threadfence();
        unsigned gen = *(volatile unsigned*)&g_bar_gen;
        if (atomicAdd(&g_bar_count, 1) == NBLK - 1) {
            g_bar_count = 0;
            __threadfence();
            *(volatile unsigned*)&g_bar_gen = gen + 1;
        } else {
            while (*(volatile unsigned*)&g_bar_gen == gen) { }
        }
        __threadfence();
    }
    __syncthreads();
}

__global__ void __launch_bounds__(NTHR, 1)
k_all(const float* __restrict__ query,
      const float* __restrict__ ctx,
      const float* __restrict__ kappa_prev,
      const float* __restrict__ Wq,
      const float* __restrict__ bq,
      const float* __restrict__ Ws,
      const float* __restrict__ bs,
      const float* __restrict__ W1,
      const float* __restrict__ b1,
      const float* __restrict__ W2,
      const float* __restrict__ b2,
      float* __restrict__ out)
{
    int bx = blockIdx.x;        // 0..127
    int t  = threadIdx.x;       // 0..511
    int lane = t & 31;
    int wid  = t >> 5;          // 0..15

    __shared__ union {
        struct { float W[ICR * 64]; float q[B * ICR]; } p1;               // 24 KB
        struct { float ctx[NW * DC];                                      // 14 KB
                 float red[16 * NW * 64];                                 // 28 KB
                 float hid[NW * 64];                                      // 1.75 KB
                 float qt[64]; float params[4]; } p2;
    } sm;
    __shared__ float shpart[2][H];      // 2 KB: split h-pre partials
    __shared__ float swr[3][16];
    __shared__ float swr3[NW][2];
    __shared__ float spw[NW];
    __shared__ int   s_last;

    // ================= Phase 1: query GEMM partials =========================
    {
        int m  = bx & 1;            // 0: Wq, 1: W1 query-half
        int jc = (bx >> 1) & 3;     // j-chunk (64 cols)
        int ic = bx >> 3;           // i-chunk (64 rows)
        const float* W = m ? (W1 + (size_t)DC * H) : Wq;
        int i0 = ic * ICR;
        int j0 = jc * 64;

        for (int idx = t; idx < ICR * 16; idx += NTHR) {
            int r  = idx >> 4;
            int c4 = idx & 15;
            *((float4*)&sm.p1.W[r * 64 + c4 * 4]) =
                *((const float4*)(W + (size_t)(i0 + r) * H + j0 + c4 * 4));
        }
        {
            int b8 = t >> 4;
            int c4 = t & 15;
            *((float4*)&sm.p1.q[b8 * ICR + c4 * 4]) =
                *((const float4*)(query + (size_t)b8 * DQ + i0 + c4 * 4));
        }
        __syncthreads();

        int jt = t & 15;            // 4 j's each
        int bb = t >> 4;            // batch 0..31
        float a0 = 0.f, a1 = 0.f, a2 = 0.f, a3 = 0.f;
#pragma unroll 8
        for (int i = 0; i < ICR; i++) {
            float4 w = *((const float4*)&sm.p1.W[i * 64 + jt * 4]);
            float qv = sm.p1.q[bb * ICR + i];
            a0 += qv * w.x; a1 += qv * w.y; a2 += qv * w.z; a3 += qv * w.w;
        }
        float4 r4 = make_float4(a0, a1, a2, a3);
        *((float4*)&g_pre[m][ic][bb][j0 + jt * 4]) = r4;
    }

    grid_sync();

    // ================= Phase 2: params + ctx-MLP slice + last-block finalize
    int b     = bx >> 2;
    int slice = bx & 3;

    // zero-fill this block's p_ctx chunk = exactly (batch b, slice) segment.
    // Ordered before finalize by this block's g_cnt[b] arrival + fences.
    {
        float4 z = make_float4(0.f, 0.f, 0.f, 0.f);
        ((float4*)(out + (size_t)B * DC + (size_t)bx * NTHR))[t & 127] = z;
        // (512 threads, 128 float4 = 512 floats; 4x redundant write is benign)
    }

    // h-pre reduce split 2-way (2 threads per j, 8 chunks each)
    {
        int j    = t & 255;
        int half = t >> 8;          // 0 or 1
        float part = 0.f;
#pragma unroll
        for (int ic = 0; ic < 8; ic++)
            part += g_pre[0][half * 8 + ic][b][j];
        shpart[half][j] = part;
    }
    // qtot for this slice (t<64)
    if (t < 64) {
        int j = slice * 64 + t;
        float qt = b1[j];
#pragma unroll
        for (int ic = 0; ic < NIC; ic++) qt += g_pre[1][ic][b][j];
        sm.p2.qt[t] = qt;
    }
    __syncthreads();

    float hval = 0.f;
    if (t < H)
        hval = tanhf(shpart[0][t] + shpart[1][t] + bq[t]);

    // stat = h @ Ws + bs
    float v0 = 0.f, v1 = 0.f, v2 = 0.f;
    if (t < H) {
        v0 = hval * Ws[t * 3 + 0];
        v1 = hval * Ws[t * 3 + 1];
        v2 = hval * Ws[t * 3 + 2];
    }
#pragma unroll
    for (int o = 16; o; o >>= 1) {
        v0 += __shfl_down_sync(0xffffffffu, v0, o);
        v1 += __shfl_down_sync(0xffffffffu, v1, o);
        v2 += __shfl_down_sync(0xffffffffu, v2, o);
    }
    if (lane == 0) { swr[0][wid] = v0; swr[1][wid] = v1; swr[2][wid] = v2; }
    __syncthreads();
    if (t == 0) {
        float s0 = bs[0], s1 = bs[1], s2 = bs[2];
#pragma unroll
        for (int w = 0; w < 16; w++) { s0 += swr[0][w]; s1 += swr[1][w]; s2 += swr[2][w]; }
        float kappa = expf(s2) + kappa_prev[b];
        sm.p2.params[0] = expf(s0);
        sm.p2.params[1] = expf(s1);
        sm.p2.params[2] = kappa;
        sm.p2.params[3] = rintf(kappa);     // jnp.round = round-half-even
    }
    __syncthreads();
    int center = (int)sm.p2.params[3];

    // stage 7 ctx rows (zero-filled out of range)
    for (int c = t; c < NW * (DC / 4); c += NTHR) {
        int w  = c / (DC / 4);
        int i4 = c % (DC / 4);
        int l  = center - 3 + w;
        float4 v = make_float4(0.f, 0.f, 0.f, 0.f);
        if (l >= 0 && l < L)
            v = ((const float4*)(ctx + ((size_t)b * L + l) * DC))[i4];
        *((float4*)&sm.p2.ctx[w * DC + i4 * 4]) = v;
    }
    __syncthreads();

    // ctx-MLP: 32 i-groups x 16 j-threads (4 j each)
    {
        int igp = t >> 4;           // 0..31, 16 i-rows each
        int jt  = t & 15;
        int j0  = slice * 64 + jt * 4;
        int i0  = igp * 16;

        float ac[NW][4];
#pragma unroll
        for (int w = 0; w < NW; w++)
#pragma unroll
            for (int k = 0; k < 4; k++) ac[w][k] = 0.f;

#pragma unroll 4
        for (int ii = 0; ii < 16; ii++) {
            float4 wv = *((const float4*)(W1 + (size_t)(i0 + ii) * H + j0));
#pragma unroll
            for (int w = 0; w < NW; w++) {
                float c = sm.p2.ctx[w * DC + i0 + ii];
                ac[w][0] += c * wv.x;
                ac[w][1] += c * wv.y;
                ac[w][2] += c * wv.z;
                ac[w][3] += c * wv.w;
            }
        }

        // fold igp pairs within warp (lanes 0-15 keep), dump once
#pragma unroll
        for (int w = 0; w < NW; w++)
#pragma unroll
            for (int k = 0; k < 4; k++) {
                float v = ac[w][k];
                v += __shfl_xor_sync(0xffffffffu, v, 16);
                if (lane < 16)
                    sm.p2.red[(wid * NW + w) * 64 + jt * 4 + k] = v;
            }
    }
    __syncthreads();

    // single pass: 448 threads finish all 7 windows
    {
        float contrib = 0.f;
        if (t < NW * 64) {
            int w = t >> 6;
            int j = t & 63;
            float hsum = sm.p2.qt[j];
#pragma unroll
            for (int p = 0; p < 16; p++)
                hsum += sm.p2.red[(p * NW + w) * 64 + j];
            contrib = tanhf(hsum) * W2[slice * 64 + j];
        }
#pragma unroll
        for (int o = 16; o; o >>= 1)
            contrib += __shfl_down_sync(0xffffffffu, contrib, o);
        if (lane == 0 && wid < NW * 2) swr3[wid >> 1][wid & 1] = contrib;
        __syncthreads();
        if (t < NW)
            g_spart[b][t][slice] = swr3[t][0] + swr3[t][1];
    }
    __syncthreads();

    // arrival counter: last slice block of this batch finalizes
    if (t == 0) {
        __threadfence();
        unsigned old = atomicAdd(&g_cnt[b], 1u);
        s_last = ((old & 3u) == 3u);
    }
    __syncthreads();
    if (!s_last) return;

    // ================= finalize (winner block; sctx already in smem) =======
    if (t == 0) {
        __threadfence();    // acquire: other slices' g_spart + zero-fill stores
        float alpha = sm.p2.params[0], beta = sm.p2.params[1], kappa = sm.p2.params[2];
        float b2v = b2[0];
        float pw[NW], psum = 0.f;
#pragma unroll
        for (int w = 0; w < NW; w++) {
            int l = center - 3 + w;
            float p = 0.f;
            if (l >= 0 && l < L) {
                float sc = b2v;
#pragma unroll
                for (int s2 = 0; s2 < 4; s2++) sc += *(volatile float*)&g_spart[b][w][s2];
                float d = (float)l - kappa;
                p = alpha * expf(sc - beta * d * d);
            }
            pw[w] = p;
            psum += p;
        }
        float inv = 1.f / psum;
#pragma unroll
        for (int w = 0; w < NW; w++) spw[w] = pw[w] * inv;
    }
    __syncthreads();

    // expected_ctx from smem-staged ctx rows (512 threads = DC)
    {
        float acc = 0.f;
#pragma unroll
        for (int w = 0; w < NW; w++)
            acc += spw[w] * sm.p2.ctx[w * DC + t];
        out[(size_t)b * DC + t] = acc;
    }
    // sparse p_ctx writes (row zero-filled by batch b's own 4 slice blocks,
    // ordered before this point by their g_cnt[b] arrivals + fences)
    if (t < NW) {
        int l = center - 3 + t;
        if (l >= 0 && l < L)
            out[(size_t)B * DC + (size_t)b * L + l] = spw[t];
    }
}

// ---------------------------------------------------------------------------
extern "C" void kernel_launch(void* const* d_in, const int* in_sizes, int n_in,
                              void* d_out, int out_size)
{
    const float* query = (const float*)d_in[0];
    const float* ctx   = (const float*)d_in[1];
    const float* kprev = (const float*)d_in[2];
    const float* Wq    = (const float*)d_in[3];
    const float* bq    = (const float*)d_in[4];
    const float* Ws    = (const float*)d_in[5];
    const float* bs    = (const float*)d_in[6];
    const float* W1    = (const float*)d_in[7];
    const float* b1    = (const float*)d_in[8];
    const float* W2    = (const float*)d_in[9];
    const float* b2    = (const float*)d_in[10];

    k_all<<<NBLK, NTHR>>>(query, ctx, kprev, Wq, bq, Ws, bs, W1, b1, W2, b2,
                          (float*)d_out);
}